// round 13
// baseline (speedup 1.0000x reference)
#include <cuda_runtime.h>
#include <cuda_fp16.h>
#include <math.h>
#include <stdint.h>

#define NB     4096
#define NROWS  8192
#define DDIM   128
#define NTILE  64          // 8192 / 128
#define NCTA   1056        // pairs of column-tiles per row: sum ceil((64-bi)/2)
#define E2LOG2 2.885390081777927f   // 2 * log2(e)

// ---------------- static scratch (no allocations allowed) ----------------
__device__ uint8_t g8[NROWS * DDIM];    // e4m3 normalized reps
__device__ float   g_rowsum[NROWS];
__device__ float   g_pos[NROWS];
__device__ float   g_self[NROWS];

// ---------------- helpers ----------------
__device__ __forceinline__ uint32_t smem_u32(const void* p) {
    uint32_t a;
    asm("{ .reg .u64 t; cvta.to.shared.u64 t, %1; cvt.u32.u64 %0, t; }"
        : "=r"(a) : "l"(p));
    return a;
}
__device__ __forceinline__ void ldsm4(uint32_t* r, uint32_t addr) {
    asm volatile("ldmatrix.sync.aligned.m8n8.x4.shared.b16 {%0,%1,%2,%3}, [%4];"
                 : "=r"(r[0]), "=r"(r[1]), "=r"(r[2]), "=r"(r[3]) : "r"(addr));
}
// fp8 e4m3 MMA, f16 accumulate (acc = 2x f16x2)
__device__ __forceinline__ void mma_f8h(uint32_t* d, const uint32_t* a,
                                        uint32_t b0, uint32_t b1) {
    asm volatile("mma.sync.aligned.m16n8k32.row.col.f16.e4m3.e4m3.f16 "
                 "{%0,%1}, {%2,%3,%4,%5}, {%6,%7}, {%0,%1};"
                 : "+r"(d[0]), "+r"(d[1])
                 : "r"(a[0]), "r"(a[1]), "r"(a[2]), "r"(a[3]), "r"(b0), "r"(b1));
}
__device__ __forceinline__ uint32_t hmul2(uint32_t a, uint32_t b) {
    uint32_t o; asm("mul.rn.f16x2 %0, %1, %2;" : "=r"(o) : "r"(a), "r"(b)); return o;
}
__device__ __forceinline__ uint32_t hadd2(uint32_t a, uint32_t b) {
    uint32_t o; asm("add.rn.f16x2 %0, %1, %2;" : "=r"(o) : "r"(a), "r"(b)); return o;
}
__device__ __forceinline__ uint32_t hex2(uint32_t a) {
    uint32_t o; asm("ex2.approx.f16x2 %0, %1;" : "=r"(o) : "r"(a)); return o;
}
__device__ __forceinline__ float2 h2f2(uint32_t h) {
    __half2 v = *reinterpret_cast<__half2*>(&h);
    return __half22float2(v);
}
// pack 4 f32 -> 4 e4m3 bytes (byte0 = x)
__device__ __forceinline__ uint32_t pack_e4m3x4(float x, float y, float z, float w) {
    uint16_t lo, hi;
    asm("cvt.rn.satfinite.e4m3x2.f32 %0, %1, %2;" : "=h"(lo) : "f"(y), "f"(x));
    asm("cvt.rn.satfinite.e4m3x2.f32 %0, %1, %2;" : "=h"(hi) : "f"(w), "f"(z));
    return (uint32_t)lo | ((uint32_t)hi << 16);
}
__device__ __forceinline__ void cp16(uint32_t dst, const void* src) {
    asm volatile("cp.async.cg.shared.global [%0], [%1], 16;"
                 :: "r"(dst), "l"(src) : "memory");
}
#define CP_COMMIT() asm volatile("cp.async.commit_group;" ::: "memory")
#define CP_WAIT1()  asm volatile("cp.async.wait_group 1;" ::: "memory")
#define CP_WAIT0()  asm volatile("cp.async.wait_group 0;" ::: "memory")

// smem: A + B0 + B1 fp8 tiles (128 rows, pitch 144 = 9x16B, conflict-free ldmatrix)
#define PITCH    144
#define SM_A     0
#define SM_B0    (128 * PITCH)
#define SM_B1    (256 * PITCH)
#define SM_ROWS  (384 * PITCH)
#define SM_COLS0 (SM_ROWS + 512)
#define SM_COLS1 (SM_COLS0 + 512)
#define SMEM_SZ  (SM_COLS1 + 512)

// ---------------- K1: normalize pair + e4m3 + positives/self ----------------
__global__ void __launch_bounds__(256) k_norm(const float* __restrict__ p1,
                                              const float* __restrict__ p2,
                                              float* __restrict__ out) {
    int gw = (blockIdx.x * blockDim.x + threadIdx.x) >> 5;   // pair index 0..NB-1
    int lane = threadIdx.x & 31;
    if (gw >= NB) return;
    if (gw == 0 && lane == 0) out[0] = 0.0f;
    float4 v1 = *(const float4*)(p1 + (size_t)gw * DDIM + lane * 4);
    float4 v2 = *(const float4*)(p2 + (size_t)gw * DDIM + lane * 4);
    float ss1 = v1.x*v1.x + v1.y*v1.y + v1.z*v1.z + v1.w*v1.w;
    float ss2 = v2.x*v2.x + v2.y*v2.y + v2.z*v2.z + v2.w*v2.w;
    float cx  = v1.x*v2.x + v1.y*v2.y + v1.z*v2.z + v1.w*v2.w;
#pragma unroll
    for (int o = 16; o; o >>= 1) {
        ss1 += __shfl_xor_sync(0xffffffffu, ss1, o);
        ss2 += __shfl_xor_sync(0xffffffffu, ss2, o);
        cx  += __shfl_xor_sync(0xffffffffu, cx,  o);
    }
    float inv1 = 1.0f / fmaxf(sqrtf(ss1), 1e-12f);
    float inv2 = 1.0f / fmaxf(sqrtf(ss2), 1e-12f);

    *(uint32_t*)(g8 + (size_t)gw * DDIM + lane * 4) =
        pack_e4m3x4(v1.x * inv1, v1.y * inv1, v1.z * inv1, v1.w * inv1);
    *(uint32_t*)(g8 + (size_t)(gw + NB) * DDIM + lane * 4) =
        pack_e4m3x4(v2.x * inv2, v2.y * inv2, v2.z * inv2, v2.w * inv2);

    if (lane == 0) {
        float pos = cx * inv1 * inv2;
        g_pos[gw] = pos;            g_pos[gw + NB] = pos;
        g_self[gw] = ss1 * inv1 * inv1;
        g_self[gw + NB] = ss2 * inv2 * inv2;
        g_rowsum[gw] = 0.0f;        g_rowsum[gw + NB] = 0.0f;
    }
}

// ---------------- K2: FP8 MMA sim-GEMM, 2 column-tiles per CTA ----------------
extern __shared__ char smem_raw[];

__global__ void __launch_bounds__(256, 3) k_gemm() {
    const int tid  = threadIdx.x;
    const int wid  = tid >> 5;
    const int lane = tid & 31;

    // decode: row bi, pair start bj0 = bi + 2*rem
    int rem = blockIdx.x;
    int bi = 0;
    while (rem >= ((65 - bi) >> 1)) { rem -= (65 - bi) >> 1; ++bi; }
    const int bj0  = bi + 2 * rem;
    const bool has2  = (bj0 + 1 < NTILE);
    const int bj1  = has2 ? bj0 + 1 : bj0;   // clamp; tile1 skipped if !has2
    const bool diag0 = (bj0 == bi);
    const int r0 = bi * 128;

    const uint32_t sb = smem_u32(smem_raw);
    float* smrows  = (float*)(smem_raw + SM_ROWS);
    float* smcols0 = (float*)(smem_raw + SM_COLS0);
    float* smcols1 = (float*)(smem_raw + SM_COLS1);
    if (tid < 128) { smrows[tid] = 0.0f; smcols0[tid] = 0.0f; smcols1[tid] = 0.0f; }

    // group 0: A rows (r0..+127) + B0 rows (bj0*128..+127)
#pragma unroll
    for (int it = 0; it < 8; ++it) {
        int idx = tid + it * 256;
        int row = idx >> 3;
        int seg = idx & 7;
        int grow = (row < 128) ? r0 + row : bj0 * 128 + (row - 128);
        cp16(sb + (uint32_t)(row * PITCH + seg * 16),
             g8 + (size_t)grow * DDIM + seg * 16);
    }
    CP_COMMIT();
    // group 1: B1 rows (bj1*128..+127) — lands during tile-0 compute
#pragma unroll
    for (int it = 0; it < 4; ++it) {
        int idx = tid + it * 256;
        int row = idx >> 3;
        int seg = idx & 7;
        cp16(sb + SM_B1 + (uint32_t)(row * PITCH + seg * 16),
             g8 + (size_t)(bj1 * 128 + row) * DDIM + seg * 16);
    }
    CP_COMMIT();
    CP_WAIT1();                 // A + B0 ready (B1 may still be in flight)
    __syncthreads();

    const int wm = wid >> 2;          // 0..1 -> rows 64*wm
    const int wn = wid & 3;           // 0..3 -> cols 32*wn

    const uint32_t a_base = sb +
        (uint32_t)((64 * wm + (lane & 15)) * PITCH + (lane >> 4) * 16);
    const int brow = 32 * wn + (lane & 7) + ((lane >> 4) << 3);
    const uint32_t b_off = (uint32_t)(brow * PITCH + ((lane >> 3) & 1) * 16);

    const __half2 sc2h = __float2half2_rn(E2LOG2);
    const uint32_t sc2 = *reinterpret_cast<const uint32_t*>(&sc2h);

    float rowacc[4][2];               // per-mi (slo, shi) accumulated across tiles
#pragma unroll
    for (int mi = 0; mi < 4; ++mi) { rowacc[mi][0] = 0.0f; rowacc[mi][1] = 0.0f; }

    // process one 128x128 tile against the resident A panel
    auto do_tile = [&](uint32_t bbuf, float* smcols, bool do_cols) {
        const uint32_t b_base = sb + bbuf + b_off;
        uint32_t acc[4][4][2];
#pragma unroll
        for (int mi = 0; mi < 4; ++mi)
#pragma unroll
            for (int nj = 0; nj < 4; ++nj) { acc[mi][nj][0] = 0u; acc[mi][nj][1] = 0u; }

#pragma unroll
        for (int kk = 0; kk < 4; ++kk) {             // 4 k-blocks of 32
            uint32_t b0[4], b1[4];
            ldsm4(b0, b_base + kk * 32);
            ldsm4(b1, b_base + 16 * PITCH + kk * 32);
#pragma unroll
            for (int mi = 0; mi < 4; ++mi) {
                uint32_t a[4];
                ldsm4(a, a_base + kk * 32 + mi * 16 * PITCH);
                mma_f8h(acc[mi][0], a, b0[0], b0[1]);
                mma_f8h(acc[mi][1], a, b0[2], b0[3]);
                mma_f8h(acc[mi][2], a, b1[0], b1[1]);
                mma_f8h(acc[mi][3], a, b1[2], b1[3]);
            }
        }

        // exp(2*sim) in f16x2
#pragma unroll
        for (int mi = 0; mi < 4; ++mi)
#pragma unroll
            for (int nj = 0; nj < 4; ++nj) {
                acc[mi][nj][0] = hex2(hmul2(acc[mi][nj][0], sc2));
                acc[mi][nj][1] = hex2(hmul2(acc[mi][nj][1], sc2));
            }

        // accumulate row partials into registers (flush once per CTA)
#pragma unroll
        for (int mi = 0; mi < 4; ++mi) {
            uint32_t hlo = hadd2(hadd2(acc[mi][0][0], acc[mi][1][0]),
                                 hadd2(acc[mi][2][0], acc[mi][3][0]));
            uint32_t hhi = hadd2(hadd2(acc[mi][0][1], acc[mi][1][1]),
                                 hadd2(acc[mi][2][1], acc[mi][3][1]));
            float2 flo = h2f2(hlo), fhi = h2f2(hhi);
            rowacc[mi][0] += flo.x + flo.y;
            rowacc[mi][1] += fhi.x + fhi.y;
        }

        // column partials (transpose-row credit)
        if (do_cols) {
#pragma unroll
            for (int nj = 0; nj < 4; ++nj) {
                uint32_t v2 = hadd2(hadd2(acc[0][nj][0], acc[0][nj][1]),
                                    hadd2(acc[1][nj][0], acc[1][nj][1]));
                v2 = hadd2(v2, hadd2(hadd2(acc[2][nj][0], acc[2][nj][1]),
                                     hadd2(acc[3][nj][0], acc[3][nj][1])));
                float2 f = h2f2(v2);
                float ve = f.x, vo = f.y;
                ve += __shfl_down_sync(0xffffffffu, ve, 16);
                ve += __shfl_down_sync(0xffffffffu, ve, 8);
                ve += __shfl_down_sync(0xffffffffu, ve, 4);
                vo += __shfl_down_sync(0xffffffffu, vo, 16);
                vo += __shfl_down_sync(0xffffffffu, vo, 8);
                vo += __shfl_down_sync(0xffffffffu, vo, 4);
                if (lane < 4) {
                    atomicAdd(&smcols[32 * wn + 8 * nj + lane * 2],     ve);
                    atomicAdd(&smcols[32 * wn + 8 * nj + lane * 2 + 1], vo);
                }
            }
        }
    };

    do_tile(SM_B0, smcols0, !diag0);

    CP_WAIT0();                 // B1 ready
    __syncthreads();
    if (has2) do_tile(SM_B1, smcols1, true);

    // flush accumulated row partials: quad shfl-reduce, 1 smem atomic/row/quad
    const int rbase = 64 * wm + (lane >> 2);
#pragma unroll
    for (int mi = 0; mi < 4; ++mi) {
        float slo = rowacc[mi][0], shi = rowacc[mi][1];
        slo += __shfl_xor_sync(0xffffffffu, slo, 1);
        slo += __shfl_xor_sync(0xffffffffu, slo, 2);
        shi += __shfl_xor_sync(0xffffffffu, shi, 1);
        shi += __shfl_xor_sync(0xffffffffu, shi, 2);
        if ((lane & 3) == 0) {
            atomicAdd(&smrows[rbase + 16 * mi],     slo);
            atomicAdd(&smrows[rbase + 16 * mi + 8], shi);
        }
    }
    __syncthreads();
    if (tid < 128) {
        atomicAdd(&g_rowsum[r0 + tid], smrows[tid]);
        if (!diag0) atomicAdd(&g_rowsum[bj0 * 128 + tid], smcols0[tid]);
        if (has2)   atomicAdd(&g_rowsum[bj1 * 128 + tid], smcols1[tid]);
    }
}

// ---------------- K3: final reduction (8 blocks + atomic) ----------------
__global__ void __launch_bounds__(1024) k_final(float* __restrict__ out) {
    __shared__ float red[1024];
    int tid = threadIdx.x;
    int r = blockIdx.x * 1024 + tid;
    float den = g_rowsum[r] - exp2f(E2LOG2 * g_self[r]);
    red[tid] = __logf(den) - 2.0f * g_pos[r];
    __syncthreads();
#pragma unroll
    for (int o = 512; o; o >>= 1) {
        if (tid < o) red[tid] += red[tid + o];
        __syncthreads();
    }
    if (tid == 0) atomicAdd(out, red[0] * (1.0f / (float)NROWS));
}

// ---------------- launcher ----------------
extern "C" void kernel_launch(void* const* d_in, const int* in_sizes, int n_in,
                              void* d_out, int out_size) {
    const float* p1 = (const float*)d_in[0];
    const float* p2 = (const float*)d_in[1];
    float* out = (float*)d_out;

    cudaFuncSetAttribute(k_gemm, cudaFuncAttributeMaxDynamicSharedMemorySize, SMEM_SZ);

    k_norm<<<NB / 8, 256>>>(p1, p2, out);
    k_gemm<<<NCTA, 256, SMEM_SZ>>>();
    k_final<<<NROWS / 1024, 1024>>>(out);
}

// round 14
// speedup vs baseline: 1.0997x; 1.0997x over previous
#include <cuda_runtime.h>
#include <cuda_fp16.h>
#include <math.h>
#include <stdint.h>

#define NB     4096
#define NROWS  8192
#define DDIM   128
#define NTILE  64          // 8192 / 128
#define NCTA   2080        // NTILE*(NTILE+1)/2 upper-triangle tiles
#define E2LOG2 2.885390081777927f   // 2 * log2(e)

// ---------------- static scratch (no allocations allowed) ----------------
__device__ uint8_t g8[NROWS * DDIM];    // e4m3 normalized reps
__device__ float   g_rowsum[NROWS];
__device__ float   g_pos[NROWS];
__device__ float   g_self[NROWS];

// ---------------- helpers ----------------
__device__ __forceinline__ uint32_t smem_u32(const void* p) {
    uint32_t a;
    asm("{ .reg .u64 t; cvta.to.shared.u64 t, %1; cvt.u32.u64 %0, t; }"
        : "=r"(a) : "l"(p));
    return a;
}
__device__ __forceinline__ void ldsm4(uint32_t* r, uint32_t addr) {
    asm volatile("ldmatrix.sync.aligned.m8n8.x4.shared.b16 {%0,%1,%2,%3}, [%4];"
                 : "=r"(r[0]), "=r"(r[1]), "=r"(r[2]), "=r"(r[3]) : "r"(addr));
}
// fp8 e4m3 MMA, f16 accumulate (acc = 2x f16x2)
__device__ __forceinline__ void mma_f8h(uint32_t* d, const uint32_t* a,
                                        uint32_t b0, uint32_t b1) {
    asm volatile("mma.sync.aligned.m16n8k32.row.col.f16.e4m3.e4m3.f16 "
                 "{%0,%1}, {%2,%3,%4,%5}, {%6,%7}, {%0,%1};"
                 : "+r"(d[0]), "+r"(d[1])
                 : "r"(a[0]), "r"(a[1]), "r"(a[2]), "r"(a[3]), "r"(b0), "r"(b1));
}
__device__ __forceinline__ uint32_t hmul2(uint32_t a, uint32_t b) {
    uint32_t o; asm("mul.rn.f16x2 %0, %1, %2;" : "=r"(o) : "r"(a), "r"(b)); return o;
}
__device__ __forceinline__ uint32_t hadd2(uint32_t a, uint32_t b) {
    uint32_t o; asm("add.rn.f16x2 %0, %1, %2;" : "=r"(o) : "r"(a), "r"(b)); return o;
}
__device__ __forceinline__ uint32_t hex2(uint32_t a) {
    uint32_t o; asm("ex2.approx.f16x2 %0, %1;" : "=r"(o) : "r"(a)); return o;
}
__device__ __forceinline__ float2 h2f2(uint32_t h) {
    __half2 v = *reinterpret_cast<__half2*>(&h);
    return __half22float2(v);
}
// pack 4 f32 -> 4 e4m3 bytes (byte0 = x)
__device__ __forceinline__ uint32_t pack_e4m3x4(float x, float y, float z, float w) {
    uint16_t lo, hi;
    asm("cvt.rn.satfinite.e4m3x2.f32 %0, %1, %2;" : "=h"(lo) : "f"(y), "f"(x));
    asm("cvt.rn.satfinite.e4m3x2.f32 %0, %1, %2;" : "=h"(hi) : "f"(w), "f"(z));
    return (uint32_t)lo | ((uint32_t)hi << 16);
}
__device__ __forceinline__ void cp16(uint32_t dst, const void* src) {
    asm volatile("cp.async.cg.shared.global [%0], [%1], 16;"
                 :: "r"(dst), "l"(src) : "memory");
}
#define CP_COMMIT() asm volatile("cp.async.commit_group;" ::: "memory")
#define CP_WAIT0()  asm volatile("cp.async.wait_group 0;" ::: "memory")

// smem: 128-row A + 128-row B fp8 tiles only, pitch 144 B (9x16B, conflict-free)
#define PITCH    144
#define SM_A     0
#define SM_B     (128 * PITCH)
#define SMEM_SZ  (256 * PITCH)

// ---------------- K1: normalize pair + e4m3 + positives/self ----------------
__global__ void __launch_bounds__(256) k_norm(const float* __restrict__ p1,
                                              const float* __restrict__ p2,
                                              float* __restrict__ out) {
    int gw = (blockIdx.x * blockDim.x + threadIdx.x) >> 5;   // pair index 0..NB-1
    int lane = threadIdx.x & 31;
    if (gw >= NB) return;
    if (gw == 0 && lane == 0) out[0] = 0.0f;
    float4 v1 = *(const float4*)(p1 + (size_t)gw * DDIM + lane * 4);
    float4 v2 = *(const float4*)(p2 + (size_t)gw * DDIM + lane * 4);
    float ss1 = v1.x*v1.x + v1.y*v1.y + v1.z*v1.z + v1.w*v1.w;
    float ss2 = v2.x*v2.x + v2.y*v2.y + v2.z*v2.z + v2.w*v2.w;
    float cx  = v1.x*v2.x + v1.y*v2.y + v1.z*v2.z + v1.w*v2.w;
#pragma unroll
    for (int o = 16; o; o >>= 1) {
        ss1 += __shfl_xor_sync(0xffffffffu, ss1, o);
        ss2 += __shfl_xor_sync(0xffffffffu, ss2, o);
        cx  += __shfl_xor_sync(0xffffffffu, cx,  o);
    }
    float inv1 = 1.0f / fmaxf(sqrtf(ss1), 1e-12f);
    float inv2 = 1.0f / fmaxf(sqrtf(ss2), 1e-12f);

    *(uint32_t*)(g8 + (size_t)gw * DDIM + lane * 4) =
        pack_e4m3x4(v1.x * inv1, v1.y * inv1, v1.z * inv1, v1.w * inv1);
    *(uint32_t*)(g8 + (size_t)(gw + NB) * DDIM + lane * 4) =
        pack_e4m3x4(v2.x * inv2, v2.y * inv2, v2.z * inv2, v2.w * inv2);

    if (lane == 0) {
        float pos = cx * inv1 * inv2;
        g_pos[gw] = pos;            g_pos[gw + NB] = pos;
        g_self[gw] = ss1 * inv1 * inv1;
        g_self[gw + NB] = ss2 * inv2 * inv2;
        g_rowsum[gw] = 0.0f;        g_rowsum[gw + NB] = 0.0f;
    }
}

// ---------------- K2: FP8 MMA (f16 acc) sim-GEMM, direct REDG epilogue ----------------
extern __shared__ char smem_raw[];

__global__ void __launch_bounds__(256, 3) k_gemm() {
    const int tid  = threadIdx.x;
    const int wid  = tid >> 5;
    const int lane = tid & 31;

    // decode upper-triangle tile (bi <= bj) from linear blockIdx
    int t = blockIdx.x;
    int bi = (int)(64.5f - sqrtf(64.5f * 64.5f - 2.0f * (float)t));
    while (bi * NTILE - (bi * (bi - 1)) / 2 > t) --bi;
    while ((bi + 1) * NTILE - ((bi + 1) * bi) / 2 <= t) ++bi;
    const int bj = bi + (t - (bi * NTILE - (bi * (bi - 1)) / 2));
    const bool diag = (bi == bj);
    const int r0 = bi * 128;
    const int c0 = bj * 128;

    const uint32_t sb = smem_u32(smem_raw);

    // async load A (rows r0..+127) + B (rows c0..+127): 256 rows x 8 segs of 16B
#pragma unroll
    for (int it = 0; it < 8; ++it) {
        int idx = tid + it * 256;
        int row = idx >> 3;
        int seg = idx & 7;
        int grow = (row < 128) ? r0 + row : c0 + (row - 128);
        cp16(sb + (uint32_t)(row * PITCH + seg * 16),
             g8 + (size_t)grow * DDIM + seg * 16);
    }
    CP_COMMIT();
    CP_WAIT0();
    __syncthreads();

    const int wm = wid >> 2;          // 0..1 -> rows 64*wm
    const int wn = wid & 3;           // 0..3 -> cols 32*wn

    const uint32_t a_base = sb +
        (uint32_t)((64 * wm + (lane & 15)) * PITCH + (lane >> 4) * 16);
    const int brow = 32 * wn + (lane & 7) + ((lane >> 4) << 3);
    const uint32_t b_base = sb + SM_B +
        (uint32_t)(brow * PITCH + ((lane >> 3) & 1) * 16);

    uint32_t acc[4][4][2];            // f16x2 accumulators
#pragma unroll
    for (int mi = 0; mi < 4; ++mi)
#pragma unroll
        for (int nj = 0; nj < 4; ++nj) { acc[mi][nj][0] = 0u; acc[mi][nj][1] = 0u; }

#pragma unroll
    for (int kk = 0; kk < 4; ++kk) {           // 4 k-blocks of 32
        uint32_t b0[4], b1[4];
        ldsm4(b0, b_base + kk * 32);           // cols 0-15 of this warp's 32
        ldsm4(b1, b_base + 16 * PITCH + kk * 32);  // cols 16-31
#pragma unroll
        for (int mi = 0; mi < 4; ++mi) {
            uint32_t a[4];
            ldsm4(a, a_base + kk * 32 + mi * 16 * PITCH);
            mma_f8h(acc[mi][0], a, b0[0], b0[1]);
            mma_f8h(acc[mi][1], a, b0[2], b0[3]);
            mma_f8h(acc[mi][2], a, b1[0], b1[1]);
            mma_f8h(acc[mi][3], a, b1[2], b1[3]);
        }
    }

    // exp(2*sim) = exp2(E2LOG2 * sim) in f16x2 (2 exps per MUFU op)
    const __half2 sc2h = __float2half2_rn(E2LOG2);
    const uint32_t sc2 = *reinterpret_cast<const uint32_t*>(&sc2h);
#pragma unroll
    for (int mi = 0; mi < 4; ++mi)
#pragma unroll
        for (int nj = 0; nj < 4; ++nj) {
            acc[mi][nj][0] = hex2(hmul2(acc[mi][nj][0], sc2));
            acc[mi][nj][1] = hex2(hmul2(acc[mi][nj][1], sc2));
        }

    // row partial sums: f16x2 tree, quad shfl-reduce, direct global REDG
    const int rbase = r0 + 64 * wm + (lane >> 2);
#pragma unroll
    for (int mi = 0; mi < 4; ++mi) {
        uint32_t hlo = hadd2(hadd2(acc[mi][0][0], acc[mi][1][0]),
                             hadd2(acc[mi][2][0], acc[mi][3][0]));
        uint32_t hhi = hadd2(hadd2(acc[mi][0][1], acc[mi][1][1]),
                             hadd2(acc[mi][2][1], acc[mi][3][1]));
        float2 flo = h2f2(hlo), fhi = h2f2(hhi);
        float slo = flo.x + flo.y;
        float shi = fhi.x + fhi.y;
        slo += __shfl_xor_sync(0xffffffffu, slo, 1);
        slo += __shfl_xor_sync(0xffffffffu, slo, 2);
        shi += __shfl_xor_sync(0xffffffffu, shi, 1);
        shi += __shfl_xor_sync(0xffffffffu, shi, 2);
        if ((lane & 3) == 0) {
            atomicAdd(&g_rowsum[rbase + 16 * mi],     slo);
            atomicAdd(&g_rowsum[rbase + 16 * mi + 8], shi);
        }
    }

    // column partial sums: direct global REDG (off-diagonal tiles only)
    if (!diag) {
#pragma unroll
        for (int nj = 0; nj < 4; ++nj) {
            uint32_t v2 = hadd2(hadd2(acc[0][nj][0], acc[0][nj][1]),
                                hadd2(acc[1][nj][0], acc[1][nj][1]));
            v2 = hadd2(v2, hadd2(hadd2(acc[2][nj][0], acc[2][nj][1]),
                                 hadd2(acc[3][nj][0], acc[3][nj][1])));
            float2 f = h2f2(v2);
            float ve = f.x, vo = f.y;   // even / odd columns
            ve += __shfl_down_sync(0xffffffffu, ve, 16);
            ve += __shfl_down_sync(0xffffffffu, ve, 8);
            ve += __shfl_down_sync(0xffffffffu, ve, 4);
            vo += __shfl_down_sync(0xffffffffu, vo, 16);
            vo += __shfl_down_sync(0xffffffffu, vo, 8);
            vo += __shfl_down_sync(0xffffffffu, vo, 4);
            if (lane < 4) {
                atomicAdd(&g_rowsum[c0 + 32 * wn + 8 * nj + lane * 2],     ve);
                atomicAdd(&g_rowsum[c0 + 32 * wn + 8 * nj + lane * 2 + 1], vo);
            }
        }
    }
}

// ---------------- K3: final reduction (8 blocks + atomic) ----------------
__global__ void __launch_bounds__(1024) k_final(float* __restrict__ out) {
    __shared__ float red[1024];
    int tid = threadIdx.x;
    int r = blockIdx.x * 1024 + tid;
    float den = g_rowsum[r] - exp2f(E2LOG2 * g_self[r]);
    red[tid] = __logf(den) - 2.0f * g_pos[r];
    __syncthreads();
#pragma unroll
    for (int o = 512; o; o >>= 1) {
        if (tid < o) red[tid] += red[tid + o];
        __syncthreads();
    }
    if (tid == 0) atomicAdd(out, red[0] * (1.0f / (float)NROWS));
}

// ---------------- launcher ----------------
extern "C" void kernel_launch(void* const* d_in, const int* in_sizes, int n_in,
                              void* d_out, int out_size) {
    const float* p1 = (const float*)d_in[0];
    const float* p2 = (const float*)d_in[1];
    float* out = (float*)d_out;

    cudaFuncSetAttribute(k_gemm, cudaFuncAttributeMaxDynamicSharedMemorySize, SMEM_SZ);

    k_norm<<<NB / 8, 256>>>(p1, p2, out);
    k_gemm<<<NCTA, 256, SMEM_SZ>>>();
    k_final<<<NROWS / 1024, 1024>>>(out);
}

// round 15
// speedup vs baseline: 1.1087x; 1.0082x over previous
#include <cuda_runtime.h>
#include <cuda_fp16.h>
#include <math.h>
#include <stdint.h>

#define NB     4096
#define NROWS  8192
#define DDIM   128
#define NTILE  64          // 8192 / 128
#define NCTA   2080        // NTILE*(NTILE+1)/2 upper-triangle tiles
#define E2LOG2 2.885390081777927f   // 2 * log2(e)

// ---------------- static scratch (no allocations allowed) ----------------
__device__ uint8_t g8a[NROWS * DDIM];   // e4m3 reps pre-scaled by 2*log2(e) (A panels)
__device__ uint8_t g8b[NROWS * DDIM];   // e4m3 reps unscaled (B panels)
__device__ float   g_rowsum[NROWS];
__device__ float   g_pos[NROWS];
__device__ float   g_self[NROWS];

// ---------------- helpers ----------------
__device__ __forceinline__ uint32_t smem_u32(const void* p) {
    uint32_t a;
    asm("{ .reg .u64 t; cvta.to.shared.u64 t, %1; cvt.u32.u64 %0, t; }"
        : "=r"(a) : "l"(p));
    return a;
}
__device__ __forceinline__ void ldsm4(uint32_t* r, uint32_t addr) {
    asm volatile("ldmatrix.sync.aligned.m8n8.x4.shared.b16 {%0,%1,%2,%3}, [%4];"
                 : "=r"(r[0]), "=r"(r[1]), "=r"(r[2]), "=r"(r[3]) : "r"(addr));
}
// fp8 e4m3 MMA, f16 accumulate (acc = 2x f16x2)
__device__ __forceinline__ void mma_f8h(uint32_t* d, const uint32_t* a,
                                        uint32_t b0, uint32_t b1) {
    asm volatile("mma.sync.aligned.m16n8k32.row.col.f16.e4m3.e4m3.f16 "
                 "{%0,%1}, {%2,%3,%4,%5}, {%6,%7}, {%0,%1};"
                 : "+r"(d[0]), "+r"(d[1])
                 : "r"(a[0]), "r"(a[1]), "r"(a[2]), "r"(a[3]), "r"(b0), "r"(b1));
}
__device__ __forceinline__ uint32_t hadd2(uint32_t a, uint32_t b) {
    uint32_t o; asm("add.rn.f16x2 %0, %1, %2;" : "=r"(o) : "r"(a), "r"(b)); return o;
}
__device__ __forceinline__ uint32_t hex2(uint32_t a) {
    uint32_t o; asm("ex2.approx.f16x2 %0, %1;" : "=r"(o) : "r"(a)); return o;
}
__device__ __forceinline__ float2 h2f2(uint32_t h) {
    __half2 v = *reinterpret_cast<__half2*>(&h);
    return __half22float2(v);
}
// pack 4 f32 -> 4 e4m3 bytes (byte0 = x)
__device__ __forceinline__ uint32_t pack_e4m3x4(float x, float y, float z, float w) {
    uint16_t lo, hi;
    asm("cvt.rn.satfinite.e4m3x2.f32 %0, %1, %2;" : "=h"(lo) : "f"(y), "f"(x));
    asm("cvt.rn.satfinite.e4m3x2.f32 %0, %1, %2;" : "=h"(hi) : "f"(w), "f"(z));
    return (uint32_t)lo | ((uint32_t)hi << 16);
}
__device__ __forceinline__ void cp16(uint32_t dst, const void* src) {
    asm volatile("cp.async.cg.shared.global [%0], [%1], 16;"
                 :: "r"(dst), "l"(src) : "memory");
}
#define CP_COMMIT() asm volatile("cp.async.commit_group;" ::: "memory")
#define CP_WAIT0()  asm volatile("cp.async.wait_group 0;" ::: "memory")

// smem: 128-row A + 128-row B fp8 tiles only, pitch 144 B (9x16B, conflict-free)
#define PITCH    144
#define SM_A     0
#define SM_B     (128 * PITCH)
#define SMEM_SZ  (256 * PITCH)

// ---------------- K1: normalize pair + e4m3 (scaled + unscaled) + pos/self ----------------
__global__ void __launch_bounds__(256) k_norm(const float* __restrict__ p1,
                                              const float* __restrict__ p2,
                                              float* __restrict__ out) {
    int gw = (blockIdx.x * blockDim.x + threadIdx.x) >> 5;   // pair index 0..NB-1
    int lane = threadIdx.x & 31;
    if (gw >= NB) return;
    if (gw == 0 && lane == 0) out[0] = 0.0f;
    float4 v1 = *(const float4*)(p1 + (size_t)gw * DDIM + lane * 4);
    float4 v2 = *(const float4*)(p2 + (size_t)gw * DDIM + lane * 4);
    float ss1 = v1.x*v1.x + v1.y*v1.y + v1.z*v1.z + v1.w*v1.w;
    float ss2 = v2.x*v2.x + v2.y*v2.y + v2.z*v2.z + v2.w*v2.w;
    float cx  = v1.x*v2.x + v1.y*v2.y + v1.z*v2.z + v1.w*v2.w;
#pragma unroll
    for (int o = 16; o; o >>= 1) {
        ss1 += __shfl_xor_sync(0xffffffffu, ss1, o);
        ss2 += __shfl_xor_sync(0xffffffffu, ss2, o);
        cx  += __shfl_xor_sync(0xffffffffu, cx,  o);
    }
    float inv1 = 1.0f / fmaxf(sqrtf(ss1), 1e-12f);
    float inv2 = 1.0f / fmaxf(sqrtf(ss2), 1e-12f);
    float sc1 = inv1 * E2LOG2;
    float sc2 = inv2 * E2LOG2;

    size_t o1 = (size_t)gw * DDIM + lane * 4;
    size_t o2 = (size_t)(gw + NB) * DDIM + lane * 4;
    *(uint32_t*)(g8b + o1) = pack_e4m3x4(v1.x*inv1, v1.y*inv1, v1.z*inv1, v1.w*inv1);
    *(uint32_t*)(g8b + o2) = pack_e4m3x4(v2.x*inv2, v2.y*inv2, v2.z*inv2, v2.w*inv2);
    *(uint32_t*)(g8a + o1) = pack_e4m3x4(v1.x*sc1,  v1.y*sc1,  v1.z*sc1,  v1.w*sc1);
    *(uint32_t*)(g8a + o2) = pack_e4m3x4(v2.x*sc2,  v2.y*sc2,  v2.z*sc2,  v2.w*sc2);

    if (lane == 0) {
        float pos = cx * inv1 * inv2;
        g_pos[gw] = pos;            g_pos[gw + NB] = pos;
        g_self[gw] = ss1 * inv1 * inv1;
        g_self[gw + NB] = ss2 * inv2 * inv2;
        g_rowsum[gw] = 0.0f;        g_rowsum[gw + NB] = 0.0f;
    }
}

// ---------------- K2: FP8 MMA (f16 acc, pre-scaled A) sim-GEMM ----------------
extern __shared__ char smem_raw[];

__global__ void __launch_bounds__(256, 3) k_gemm() {
    const int tid  = threadIdx.x;
    const int wid  = tid >> 5;
    const int lane = tid & 31;

    // decode upper-triangle tile (bi <= bj) from linear blockIdx
    int t = blockIdx.x;
    int bi = (int)(64.5f - sqrtf(64.5f * 64.5f - 2.0f * (float)t));
    while (bi * NTILE - (bi * (bi - 1)) / 2 > t) --bi;
    while ((bi + 1) * NTILE - ((bi + 1) * bi) / 2 <= t) ++bi;
    const int bj = bi + (t - (bi * NTILE - (bi * (bi - 1)) / 2));
    const bool diag = (bi == bj);
    const int r0 = bi * 128;
    const int c0 = bj * 128;

    const uint32_t sb = smem_u32(smem_raw);

    // async load A (scaled, rows r0..+127) + B (unscaled, rows c0..+127)
#pragma unroll
    for (int it = 0; it < 8; ++it) {
        int idx = tid + it * 256;
        int row = idx >> 3;
        int seg = idx & 7;
        const uint8_t* src = (row < 128)
            ? g8a + (size_t)(r0 + row) * DDIM + seg * 16
            : g8b + (size_t)(c0 + row - 128) * DDIM + seg * 16;
        cp16(sb + (uint32_t)(row * PITCH + seg * 16), src);
    }
    CP_COMMIT();
    CP_WAIT0();
    __syncthreads();

    const int wm = wid >> 2;          // 0..1 -> rows 64*wm
    const int wn = wid & 3;           // 0..3 -> cols 32*wn

    const uint32_t a_base = sb +
        (uint32_t)((64 * wm + (lane & 15)) * PITCH + (lane >> 4) * 16);
    const int brow = 32 * wn + (lane & 7) + ((lane >> 4) << 3);
    const uint32_t b_base = sb + SM_B +
        (uint32_t)(brow * PITCH + ((lane >> 3) & 1) * 16);

    uint32_t acc[4][4][2];            // f16x2 accumulators (already 2*log2e*sim)
#pragma unroll
    for (int mi = 0; mi < 4; ++mi)
#pragma unroll
        for (int nj = 0; nj < 4; ++nj) { acc[mi][nj][0] = 0u; acc[mi][nj][1] = 0u; }

#pragma unroll
    for (int kk = 0; kk < 4; ++kk) {           // 4 k-blocks of 32
        uint32_t b0[4], b1[4];
        ldsm4(b0, b_base + kk * 32);           // cols 0-15 of this warp's 32
        ldsm4(b1, b_base + 16 * PITCH + kk * 32);  // cols 16-31
#pragma unroll
        for (int mi = 0; mi < 4; ++mi) {
            uint32_t a[4];
            ldsm4(a, a_base + kk * 32 + mi * 16 * PITCH);
            mma_f8h(acc[mi][0], a, b0[0], b0[1]);
            mma_f8h(acc[mi][1], a, b0[2], b0[3]);
            mma_f8h(acc[mi][2], a, b1[0], b1[1]);
            mma_f8h(acc[mi][3], a, b1[2], b1[3]);
        }
    }

    // exp: accs are pre-scaled -> bare ex2.approx.f16x2 (2 exps per MUFU op)
#pragma unroll
    for (int mi = 0; mi < 4; ++mi)
#pragma unroll
        for (int nj = 0; nj < 4; ++nj) {
            acc[mi][nj][0] = hex2(acc[mi][nj][0]);
            acc[mi][nj][1] = hex2(acc[mi][nj][1]);
        }

    // row partial sums: f16x2 tree, quad shfl-reduce, direct global REDG
    const int rbase = r0 + 64 * wm + (lane >> 2);
#pragma unroll
    for (int mi = 0; mi < 4; ++mi) {
        uint32_t hlo = hadd2(hadd2(acc[mi][0][0], acc[mi][1][0]),
                             hadd2(acc[mi][2][0], acc[mi][3][0]));
        uint32_t hhi = hadd2(hadd2(acc[mi][0][1], acc[mi][1][1]),
                             hadd2(acc[mi][2][1], acc[mi][3][1]));
        float2 flo = h2f2(hlo), fhi = h2f2(hhi);
        float slo = flo.x + flo.y;
        float shi = fhi.x + fhi.y;
        slo += __shfl_xor_sync(0xffffffffu, slo, 1);
        slo += __shfl_xor_sync(0xffffffffu, slo, 2);
        shi += __shfl_xor_sync(0xffffffffu, shi, 1);
        shi += __shfl_xor_sync(0xffffffffu, shi, 2);
        if ((lane & 3) == 0) {
            atomicAdd(&g_rowsum[rbase + 16 * mi],     slo);
            atomicAdd(&g_rowsum[rbase + 16 * mi + 8], shi);
        }
    }

    // column partial sums: direct global REDG (off-diagonal tiles only)
    if (!diag) {
#pragma unroll
        for (int nj = 0; nj < 4; ++nj) {
            uint32_t v2 = hadd2(hadd2(acc[0][nj][0], acc[0][nj][1]),
                                hadd2(acc[1][nj][0], acc[1][nj][1]));
            v2 = hadd2(v2, hadd2(hadd2(acc[2][nj][0], acc[2][nj][1]),
                                 hadd2(acc[3][nj][0], acc[3][nj][1])));
            float2 f = h2f2(v2);
            float ve = f.x, vo = f.y;   // even / odd columns
            ve += __shfl_down_sync(0xffffffffu, ve, 16);
            ve += __shfl_down_sync(0xffffffffu, ve, 8);
            ve += __shfl_down_sync(0xffffffffu, ve, 4);
            vo += __shfl_down_sync(0xffffffffu, vo, 16);
            vo += __shfl_down_sync(0xffffffffu, vo, 8);
            vo += __shfl_down_sync(0xffffffffu, vo, 4);
            if (lane < 4) {
                atomicAdd(&g_rowsum[c0 + 32 * wn + 8 * nj + lane * 2],     ve);
                atomicAdd(&g_rowsum[c0 + 32 * wn + 8 * nj + lane * 2 + 1], vo);
            }
        }
    }
}

// ---------------- K3: final reduction (64 blocks x 128 + atomic) ----------------
__global__ void __launch_bounds__(128) k_final(float* __restrict__ out) {
    __shared__ float red[128];
    int tid = threadIdx.x;
    int r = blockIdx.x * 128 + tid;
    float den = g_rowsum[r] - exp2f(E2LOG2 * g_self[r]);
    red[tid] = __logf(den) - 2.0f * g_pos[r];
    __syncthreads();
#pragma unroll
    for (int o = 64; o; o >>= 1) {
        if (tid < o) red[tid] += red[tid + o];
        __syncthreads();
    }
    if (tid == 0) atomicAdd(out, red[0] * (1.0f / (float)NROWS));
}

// ---------------- launcher ----------------
extern "C" void kernel_launch(void* const* d_in, const int* in_sizes, int n_in,
                              void* d_out, int out_size) {
    const float* p1 = (const float*)d_in[0];
    const float* p2 = (const float*)d_in[1];
    float* out = (float*)d_out;

    cudaFuncSetAttribute(k_gemm, cudaFuncAttributeMaxDynamicSharedMemorySize, SMEM_SZ);

    k_norm<<<NB / 8, 256>>>(p1, p2, out);
    k_gemm<<<NCTA, 256, SMEM_SZ>>>();
    k_final<<<NROWS / 128, 128>>>(out);
}

// round 16
// speedup vs baseline: 1.1097x; 1.0009x over previous
#include <cuda_runtime.h>
#include <cuda_fp16.h>
#include <math.h>
#include <stdint.h>

#define NB     4096
#define NROWS  8192
#define DDIM   128
#define NTILE  64          // 8192 / 128
#define NCTA   2080        // NTILE*(NTILE+1)/2 upper-triangle tiles
#define E2LOG2 2.885390081777927f   // 2 * log2(e)
#define SQS    1.698643603f          // sqrt(2 * log2(e))

// ---------------- static scratch (no allocations allowed) ----------------
__device__ uint8_t g8s[NROWS * DDIM];   // e4m3 reps scaled by sqrt(2*log2 e)
__device__ float   g_rowsum[NROWS];
__device__ float   g_pos[NROWS];
__device__ float   g_self[NROWS];

// ---------------- helpers ----------------
__device__ __forceinline__ uint32_t smem_u32(const void* p) {
    uint32_t a;
    asm("{ .reg .u64 t; cvta.to.shared.u64 t, %1; cvt.u32.u64 %0, t; }"
        : "=r"(a) : "l"(p));
    return a;
}
__device__ __forceinline__ void ldsm4(uint32_t* r, uint32_t addr) {
    asm volatile("ldmatrix.sync.aligned.m8n8.x4.shared.b16 {%0,%1,%2,%3}, [%4];"
                 : "=r"(r[0]), "=r"(r[1]), "=r"(r[2]), "=r"(r[3]) : "r"(addr));
}
// fp8 e4m3 MMA, f16 accumulate (acc = 2x f16x2)
__device__ __forceinline__ void mma_f8h(uint32_t* d, const uint32_t* a,
                                        uint32_t b0, uint32_t b1) {
    asm volatile("mma.sync.aligned.m16n8k32.row.col.f16.e4m3.e4m3.f16 "
                 "{%0,%1}, {%2,%3,%4,%5}, {%6,%7}, {%0,%1};"
                 : "+r"(d[0]), "+r"(d[1])
                 : "r"(a[0]), "r"(a[1]), "r"(a[2]), "r"(a[3]), "r"(b0), "r"(b1));
}
__device__ __forceinline__ uint32_t hadd2(uint32_t a, uint32_t b) {
    uint32_t o; asm("add.rn.f16x2 %0, %1, %2;" : "=r"(o) : "r"(a), "r"(b)); return o;
}
__device__ __forceinline__ uint32_t hex2(uint32_t a) {
    uint32_t o; asm("ex2.approx.f16x2 %0, %1;" : "=r"(o) : "r"(a)); return o;
}
__device__ __forceinline__ float2 h2f2(uint32_t h) {
    __half2 v = *reinterpret_cast<__half2*>(&h);
    return __half22float2(v);
}
// pack 4 f32 -> 4 e4m3 bytes (byte0 = x)
__device__ __forceinline__ uint32_t pack_e4m3x4(float x, float y, float z, float w) {
    uint16_t lo, hi;
    asm("cvt.rn.satfinite.e4m3x2.f32 %0, %1, %2;" : "=h"(lo) : "f"(y), "f"(x));
    asm("cvt.rn.satfinite.e4m3x2.f32 %0, %1, %2;" : "=h"(hi) : "f"(w), "f"(z));
    return (uint32_t)lo | ((uint32_t)hi << 16);
}
__device__ __forceinline__ void cp16(uint32_t dst, const void* src) {
    asm volatile("cp.async.cg.shared.global [%0], [%1], 16;"
                 :: "r"(dst), "l"(src) : "memory");
}
#define CP_COMMIT() asm volatile("cp.async.commit_group;" ::: "memory")
#define CP_WAIT0()  asm volatile("cp.async.wait_group 0;" ::: "memory")

// smem: 128-row A + 128-row B fp8 tiles only, pitch 144 B (9x16B, conflict-free)
#define PITCH    144
#define SM_A     0
#define SM_B     (128 * PITCH)
#define SMEM_SZ  (256 * PITCH)

// ---------------- K1: normalize pair + sqrt-scaled e4m3 + pos/self ----------------
__global__ void __launch_bounds__(256) k_norm(const float* __restrict__ p1,
                                              const float* __restrict__ p2,
                                              float* __restrict__ out) {
    int gw = (blockIdx.x * blockDim.x + threadIdx.x) >> 5;   // pair index 0..NB-1
    int lane = threadIdx.x & 31;
    if (gw >= NB) return;
    if (gw == 0 && lane == 0) out[0] = 0.0f;
    float4 v1 = *(const float4*)(p1 + (size_t)gw * DDIM + lane * 4);
    float4 v2 = *(const float4*)(p2 + (size_t)gw * DDIM + lane * 4);
    float ss1 = v1.x*v1.x + v1.y*v1.y + v1.z*v1.z + v1.w*v1.w;
    float ss2 = v2.x*v2.x + v2.y*v2.y + v2.z*v2.z + v2.w*v2.w;
    float cx  = v1.x*v2.x + v1.y*v2.y + v1.z*v2.z + v1.w*v2.w;
#pragma unroll
    for (int o = 16; o; o >>= 1) {
        ss1 += __shfl_xor_sync(0xffffffffu, ss1, o);
        ss2 += __shfl_xor_sync(0xffffffffu, ss2, o);
        cx  += __shfl_xor_sync(0xffffffffu, cx,  o);
    }
    float inv1 = 1.0f / fmaxf(sqrtf(ss1), 1e-12f);
    float inv2 = 1.0f / fmaxf(sqrtf(ss2), 1e-12f);
    float sc1 = inv1 * SQS;
    float sc2 = inv2 * SQS;

    *(uint32_t*)(g8s + (size_t)gw * DDIM + lane * 4) =
        pack_e4m3x4(v1.x*sc1, v1.y*sc1, v1.z*sc1, v1.w*sc1);
    *(uint32_t*)(g8s + (size_t)(gw + NB) * DDIM + lane * 4) =
        pack_e4m3x4(v2.x*sc2, v2.y*sc2, v2.z*sc2, v2.w*sc2);

    if (lane == 0) {
        float pos = cx * inv1 * inv2;
        g_pos[gw] = pos;            g_pos[gw + NB] = pos;
        g_self[gw] = ss1 * inv1 * inv1;
        g_self[gw + NB] = ss2 * inv2 * inv2;
        g_rowsum[gw] = 0.0f;        g_rowsum[gw + NB] = 0.0f;
    }
}

// ---------------- K2: FP8 MMA sim-GEMM, packed-f16x2 epilogue ----------------
extern __shared__ char smem_raw[];

__global__ void __launch_bounds__(256, 3) k_gemm() {
    const int tid  = threadIdx.x;
    const int wid  = tid >> 5;
    const int lane = tid & 31;

    // decode upper-triangle tile (bi <= bj) from linear blockIdx
    int t = blockIdx.x;
    int bi = (int)(64.5f - sqrtf(64.5f * 64.5f - 2.0f * (float)t));
    while (bi * NTILE - (bi * (bi - 1)) / 2 > t) --bi;
    while ((bi + 1) * NTILE - ((bi + 1) * bi) / 2 <= t) ++bi;
    const int bj = bi + (t - (bi * NTILE - (bi * (bi - 1)) / 2));
    const bool diag = (bi == bj);
    const int r0 = bi * 128;
    const int c0 = bj * 128;

    const uint32_t sb = smem_u32(smem_raw);

    // async load A (rows r0..+127) + B (rows c0..+127), same scaled array
#pragma unroll
    for (int it = 0; it < 8; ++it) {
        int idx = tid + it * 256;
        int row = idx >> 3;
        int seg = idx & 7;
        int grow = (row < 128) ? r0 + row : c0 + (row - 128);
        cp16(sb + (uint32_t)(row * PITCH + seg * 16),
             g8s + (size_t)grow * DDIM + seg * 16);
    }
    CP_COMMIT();
    CP_WAIT0();
    __syncthreads();

    const int wm = wid >> 2;          // 0..1 -> rows 64*wm
    const int wn = wid & 3;           // 0..3 -> cols 32*wn

    const uint32_t a_base = sb +
        (uint32_t)((64 * wm + (lane & 15)) * PITCH + (lane >> 4) * 16);
    const int brow = 32 * wn + (lane & 7) + ((lane >> 4) << 3);
    const uint32_t b_base = sb + SM_B +
        (uint32_t)(brow * PITCH + ((lane >> 3) & 1) * 16);

    uint32_t acc[4][4][2];            // f16x2 accumulators (= 2*log2e*sim)
#pragma unroll
    for (int mi = 0; mi < 4; ++mi)
#pragma unroll
        for (int nj = 0; nj < 4; ++nj) { acc[mi][nj][0] = 0u; acc[mi][nj][1] = 0u; }

#pragma unroll
    for (int kk = 0; kk < 4; ++kk) {           // 4 k-blocks of 32
        uint32_t b0[4], b1[4];
        ldsm4(b0, b_base + kk * 32);           // cols 0-15 of this warp's 32
        ldsm4(b1, b_base + 16 * PITCH + kk * 32);  // cols 16-31
#pragma unroll
        for (int mi = 0; mi < 4; ++mi) {
            uint32_t a[4];
            ldsm4(a, a_base + kk * 32 + mi * 16 * PITCH);
            mma_f8h(acc[mi][0], a, b0[0], b0[1]);
            mma_f8h(acc[mi][1], a, b0[2], b0[3]);
            mma_f8h(acc[mi][2], a, b1[0], b1[1]);
            mma_f8h(acc[mi][3], a, b1[2], b1[3]);
        }
    }

    // exp: accs pre-scaled -> bare ex2.approx.f16x2 (2 exps per MUFU op)
#pragma unroll
    for (int mi = 0; mi < 4; ++mi)
#pragma unroll
        for (int nj = 0; nj < 4; ++nj) {
            acc[mi][nj][0] = hex2(acc[mi][nj][0]);
            acc[mi][nj][1] = hex2(acc[mi][nj][1]);
        }

    // row partial sums: packed f16x2 quad-reduce, leader converts + REDG
    const int rbase = r0 + 64 * wm + (lane >> 2);
#pragma unroll
    for (int mi = 0; mi < 4; ++mi) {
        uint32_t hlo = hadd2(hadd2(acc[mi][0][0], acc[mi][1][0]),
                             hadd2(acc[mi][2][0], acc[mi][3][0]));
        uint32_t hhi = hadd2(hadd2(acc[mi][0][1], acc[mi][1][1]),
                             hadd2(acc[mi][2][1], acc[mi][3][1]));
        hlo = hadd2(hlo, __shfl_xor_sync(0xffffffffu, hlo, 1));
        hlo = hadd2(hlo, __shfl_xor_sync(0xffffffffu, hlo, 2));
        hhi = hadd2(hhi, __shfl_xor_sync(0xffffffffu, hhi, 1));
        hhi = hadd2(hhi, __shfl_xor_sync(0xffffffffu, hhi, 2));
        if ((lane & 3) == 0) {
            float2 flo = h2f2(hlo), fhi = h2f2(hhi);
            atomicAdd(&g_rowsum[rbase + 16 * mi],     flo.x + flo.y);
            atomicAdd(&g_rowsum[rbase + 16 * mi + 8], fhi.x + fhi.y);
        }
    }

    // column partial sums: packed f16x2 octet-reduce, lanes 0-3 REDG
    if (!diag) {
#pragma unroll
        for (int nj = 0; nj < 4; ++nj) {
            uint32_t v2 = hadd2(hadd2(acc[0][nj][0], acc[0][nj][1]),
                                hadd2(acc[1][nj][0], acc[1][nj][1]));
            v2 = hadd2(v2, hadd2(hadd2(acc[2][nj][0], acc[2][nj][1]),
                                 hadd2(acc[3][nj][0], acc[3][nj][1])));
            v2 = hadd2(v2, __shfl_down_sync(0xffffffffu, v2, 16));
            v2 = hadd2(v2, __shfl_down_sync(0xffffffffu, v2, 8));
            v2 = hadd2(v2, __shfl_down_sync(0xffffffffu, v2, 4));
            if (lane < 4) {
                float2 f = h2f2(v2);
                atomicAdd(&g_rowsum[c0 + 32 * wn + 8 * nj + lane * 2],     f.x);
                atomicAdd(&g_rowsum[c0 + 32 * wn + 8 * nj + lane * 2 + 1], f.y);
            }
        }
    }
}

// ---------------- K3: final reduction (64 blocks x 128 + atomic) ----------------
__global__ void __launch_bounds__(128) k_final(float* __restrict__ out) {
    __shared__ float red[128];
    int tid = threadIdx.x;
    int r = blockIdx.x * 128 + tid;
    float den = g_rowsum[r] - exp2f(E2LOG2 * g_self[r]);
    red[tid] = __logf(den) - 2.0f * g_pos[r];
    __syncthreads();
#pragma unroll
    for (int o = 64; o; o >>= 1) {
        if (tid < o) red[tid] += red[tid + o];
        __syncthreads();
    }
    if (tid == 0) atomicAdd(out, red[0] * (1.0f / (float)NROWS));
}

// ---------------- launcher ----------------
extern "C" void kernel_launch(void* const* d_in, const int* in_sizes, int n_in,
                              void* d_out, int out_size) {
    const float* p1 = (const float*)d_in[0];
    const float* p2 = (const float*)d_in[1];
    float* out = (float*)d_out;

    cudaFuncSetAttribute(k_gemm, cudaFuncAttributeMaxDynamicSharedMemorySize, SMEM_SZ);

    k_norm<<<NB / 8, 256>>>(p1, p2, out);
    k_gemm<<<NCTA, 256, SMEM_SZ>>>();
    k_final<<<NROWS / 128, 128>>>(out);
}